// round 1
// baseline (speedup 1.0000x reference)
#include <cuda_runtime.h>
#include <math.h>

// Problem constants (fixed by reference)
#define D_MODEL 1024
#define N_HEADS 16
#define DEPTH   64
#define BATCH   2
#define SEQ     2048
#define M_TOT   (BATCH * SEQ)   // 4096

// ---------------------------------------------------------------------------
// Scratch (no cudaMalloc allowed): device globals
// ---------------------------------------------------------------------------
__device__ float g_q[BATCH * N_HEADS * SEQ * DEPTH];   // [B,H,S,64] 16 MB
__device__ float g_k[BATCH * N_HEADS * SEQ * DEPTH];
__device__ float g_v[BATCH * N_HEADS * SEQ * DEPTH];
__device__ float g_ao[M_TOT * D_MODEL];                // attention out [B,S,D]

// ---------------------------------------------------------------------------
// GEMM: Y = X @ W^T + bias.  X:[4096,1024] row-major, W:[1024,1024] row-major
// (torch Linear weight, rows are output features). Both operands K-major.
// BM=BN=64, BK=16, 256 threads, 4x4 per thread micro-tile.
// HEAD_SPLIT=1 writes output into [B,H,S,64] layout for attention.
// ---------------------------------------------------------------------------
template <int HEAD_SPLIT>
__global__ __launch_bounds__(256)
void gemm_bias_kernel(const float* __restrict__ X,
                      const float* __restrict__ W,
                      const float* __restrict__ bias,
                      float* __restrict__ Y)
{
    __shared__ float As[16][64];   // [k][m]
    __shared__ float Bs[16][64];   // [k][n]

    const int tid  = threadIdx.x;
    const int m0   = blockIdx.y * 64;
    const int n0   = blockIdx.x * 64;
    const int lrow = tid >> 2;     // 0..63   (loader row)
    const int lc4  = tid & 3;      // 0..3    (loader float4 col)
    const int ty   = tid >> 4;     // 0..15   (compute row group)
    const int tx   = tid & 15;     // 0..15   (compute col group)

    float acc[4][4] = {};

    for (int k0 = 0; k0 < D_MODEL; k0 += 16) {
        float4 xa = *(const float4*)&X[(size_t)(m0 + lrow) * D_MODEL + k0 + lc4 * 4];
        float4 wb = *(const float4*)&W[(size_t)(n0 + lrow) * D_MODEL + k0 + lc4 * 4];
        As[lc4 * 4 + 0][lrow] = xa.x;
        As[lc4 * 4 + 1][lrow] = xa.y;
        As[lc4 * 4 + 2][lrow] = xa.z;
        As[lc4 * 4 + 3][lrow] = xa.w;
        Bs[lc4 * 4 + 0][lrow] = wb.x;
        Bs[lc4 * 4 + 1][lrow] = wb.y;
        Bs[lc4 * 4 + 2][lrow] = wb.z;
        Bs[lc4 * 4 + 3][lrow] = wb.w;
        __syncthreads();

        #pragma unroll
        for (int k = 0; k < 16; k++) {
            float4 a4 = *(float4*)&As[k][ty * 4];
            float4 b4 = *(float4*)&Bs[k][tx * 4];
            float a[4] = {a4.x, a4.y, a4.z, a4.w};
            float b[4] = {b4.x, b4.y, b4.z, b4.w};
            #pragma unroll
            for (int i = 0; i < 4; i++)
                #pragma unroll
                for (int j = 0; j < 4; j++)
                    acc[i][j] += a[i] * b[j];
        }
        __syncthreads();
    }

    float4 bb = *(const float4*)&bias[n0 + tx * 4];
    const float badd[4] = {bb.x, bb.y, bb.z, bb.w};

    #pragma unroll
    for (int i = 0; i < 4; i++) {
        const int m = m0 + ty * 4 + i;
        float4 o;
        o.x = acc[i][0] + badd[0];
        o.y = acc[i][1] + badd[1];
        o.z = acc[i][2] + badd[2];
        o.w = acc[i][3] + badd[3];
        if (HEAD_SPLIT) {
            const int b  = m >> 11;         // / SEQ
            const int s  = m & (SEQ - 1);
            const int n  = n0 + tx * 4;     // 4 consecutive cols, same head
            const int h  = n >> 6;
            const int dd = n & 63;
            *(float4*)&Y[((size_t)(b * N_HEADS + h) * SEQ + s) * DEPTH + dd] = o;
        } else {
            *(float4*)&Y[(size_t)m * D_MODEL + n0 + tx * 4] = o;
        }
    }
}

// ---------------------------------------------------------------------------
// Flash attention, fp32, online softmax.
// Grid: (S/64 qblocks, B*H). Block: 256 threads.
// Thread (r = tid/4, c = tid%4) owns query row r, output cols [c*16, c*16+16).
// ---------------------------------------------------------------------------
#define BQ 64
#define BKV 64
#define LD (DEPTH + 4)   // 68 floats, keeps rows 16B aligned, breaks conflicts

__global__ __launch_bounds__(256)
void flash_attn_kernel()
{
    extern __shared__ float sm[];
    float* q_s = sm;                       // BQ * LD
    float* k_s = q_s + BQ * LD;            // BKV * LD
    float* v_s = k_s + BKV * LD;           // BKV * LD
    float* s_s = v_s + BKV * LD;           // BQ * LD (64 cols used)
    float* m_s = s_s + BQ * LD;            // BQ
    float* l_s = m_s + BQ;                 // BQ
    float* a_s = l_s + BQ;                 // BQ (alpha rescale)

    const int tid = threadIdx.x;
    const int r   = tid >> 2;   // query row in tile
    const int c   = tid & 3;    // output column quadrant

    const int qb  = blockIdx.x;
    const int bh  = blockIdx.y;            // b*N_HEADS + h
    const int q0  = qb * BQ;

    const float scale = 0.125f;            // 1/sqrt(64)

    const float* gq = g_q + ((size_t)bh * SEQ + q0) * DEPTH;
    const float* gk = g_k + (size_t)bh * SEQ * DEPTH;
    const float* gv = g_v + (size_t)bh * SEQ * DEPTH;

    // Load Q tile (64x64 floats, 4 float4 per thread)
    #pragma unroll
    for (int i = 0; i < 4; i++) {
        int idx  = tid + i * 256;   // 0..1023
        int row  = idx >> 4;
        int col4 = idx & 15;
        *(float4*)&q_s[row * LD + col4 * 4] =
            *(const float4*)&gq[row * DEPTH + col4 * 4];
    }
    if (tid < BQ) { m_s[tid] = -INFINITY; l_s[tid] = 0.0f; }

    float acc[16];
    #pragma unroll
    for (int i = 0; i < 16; i++) acc[i] = 0.0f;

    __syncthreads();

    for (int j = 0; j < SEQ / BKV; j++) {
        // Load K, V chunks
        const float* kp = gk + (size_t)j * BKV * DEPTH;
        const float* vp = gv + (size_t)j * BKV * DEPTH;
        #pragma unroll
        for (int i = 0; i < 4; i++) {
            int idx  = tid + i * 256;
            int row  = idx >> 4;
            int col4 = idx & 15;
            *(float4*)&k_s[row * LD + col4 * 4] =
                *(const float4*)&kp[row * DEPTH + col4 * 4];
            *(float4*)&v_s[row * LD + col4 * 4] =
                *(const float4*)&vp[row * DEPTH + col4 * 4];
        }
        __syncthreads();

        // Scores: s[r][c*16+ii] = scale * dot64(q[r], k[c*16+ii])
        {
            float sacc[16];
            #pragma unroll
            for (int ii = 0; ii < 16; ii++) sacc[ii] = 0.0f;
            #pragma unroll 4
            for (int kk4 = 0; kk4 < 16; kk4++) {
                float4 q4 = *(float4*)&q_s[r * LD + kk4 * 4];
                #pragma unroll
                for (int ii = 0; ii < 16; ii++) {
                    float4 k4 = *(float4*)&k_s[(c * 16 + ii) * LD + kk4 * 4];
                    sacc[ii] += q4.x * k4.x + q4.y * k4.y
                              + q4.z * k4.z + q4.w * k4.w;
                }
            }
            #pragma unroll
            for (int ii = 0; ii < 16; ii++)
                s_s[r * LD + c * 16 + ii] = sacc[ii] * scale;
        }
        __syncthreads();

        // Online softmax bookkeeping: one thread per query row
        if (tid < BQ) {
            const int rr = tid;
            float mx = m_s[rr];
            float cm = -INFINITY;
            #pragma unroll 8
            for (int k = 0; k < BKV; k++)
                cm = fmaxf(cm, s_s[rr * LD + k]);
            float mn    = fmaxf(mx, cm);
            float alpha = __expf(mx - mn);   // 0 on first chunk (mx=-inf)
            float sum   = 0.0f;
            #pragma unroll 8
            for (int k = 0; k < BKV; k++) {
                float p = __expf(s_s[rr * LD + k] - mn);
                s_s[rr * LD + k] = p;
                sum += p;
            }
            l_s[rr] = l_s[rr] * alpha + sum;
            m_s[rr] = mn;
            a_s[rr] = alpha;
        }
        __syncthreads();

        // Rescale accumulator, add P @ V
        {
            float alpha = a_s[r];
            #pragma unroll
            for (int i = 0; i < 16; i++) acc[i] *= alpha;
            #pragma unroll 4
            for (int k = 0; k < BKV; k++) {
                float p = s_s[r * LD + k];
                const float* vr = &v_s[k * LD + c * 16];
                float4 v0 = *(const float4*)&vr[0];
                float4 v1 = *(const float4*)&vr[4];
                float4 v2 = *(const float4*)&vr[8];
                float4 v3 = *(const float4*)&vr[12];
                acc[0]  += p * v0.x;  acc[1]  += p * v0.y;
                acc[2]  += p * v0.z;  acc[3]  += p * v0.w;
                acc[4]  += p * v1.x;  acc[5]  += p * v1.y;
                acc[6]  += p * v1.z;  acc[7]  += p * v1.w;
                acc[8]  += p * v2.x;  acc[9]  += p * v2.y;
                acc[10] += p * v2.z;  acc[11] += p * v2.w;
                acc[12] += p * v3.x;  acc[13] += p * v3.y;
                acc[14] += p * v3.z;  acc[15] += p * v3.w;
            }
        }
        __syncthreads();   // before reloading k_s/v_s/s_s
    }

    // Epilogue: normalize and write to [B,S,D] (heads re-interleaved)
    const float inv = 1.0f / l_s[r];
    const int b = bh >> 4;
    const int h = bh & 15;
    float* op = &g_ao[((size_t)(b * SEQ + q0 + r)) * D_MODEL + h * DEPTH + c * 16];
    #pragma unroll
    for (int i4 = 0; i4 < 4; i4++) {
        float4 o;
        o.x = acc[i4 * 4 + 0] * inv;
        o.y = acc[i4 * 4 + 1] * inv;
        o.z = acc[i4 * 4 + 2] * inv;
        o.w = acc[i4 * 4 + 3] * inv;
        *(float4*)&op[i4 * 4] = o;
    }
}

// ---------------------------------------------------------------------------
// Launch
// ---------------------------------------------------------------------------
extern "C" void kernel_launch(void* const* d_in, const int* in_sizes, int n_in,
                              void* d_out, int out_size)
{
    const float* Q  = (const float*)d_in[0];
    const float* K  = (const float*)d_in[1];
    const float* V  = (const float*)d_in[2];
    const float* Wq = (const float*)d_in[3];
    const float* bq = (const float*)d_in[4];
    const float* Wk = (const float*)d_in[5];
    const float* bk = (const float*)d_in[6];
    const float* Wv = (const float*)d_in[7];
    const float* bv = (const float*)d_in[8];
    const float* Wo = (const float*)d_in[9];
    const float* bo = (const float*)d_in[10];
    float* out = (float*)d_out;

    float *gq, *gk, *gv, *gao;
    cudaGetSymbolAddress((void**)&gq,  g_q);
    cudaGetSymbolAddress((void**)&gk,  g_k);
    cudaGetSymbolAddress((void**)&gv,  g_v);
    cudaGetSymbolAddress((void**)&gao, g_ao);

    const dim3 ggrid(D_MODEL / 64, M_TOT / 64);   // (16, 64)
    const dim3 gblk(256);

    // Projections -> head-split scratch
    gemm_bias_kernel<1><<<ggrid, gblk>>>(Q, Wq, bq, gq);
    gemm_bias_kernel<1><<<ggrid, gblk>>>(K, Wk, bk, gk);
    gemm_bias_kernel<1><<<ggrid, gblk>>>(V, Wv, bv, gv);

    // Flash attention
    const int smem_bytes = (4 * BQ * LD + 3 * BQ) * (int)sizeof(float); // 70400
    cudaFuncSetAttribute(flash_attn_kernel,
                         cudaFuncAttributeMaxDynamicSharedMemorySize, smem_bytes);
    flash_attn_kernel<<<dim3(SEQ / BQ, BATCH * N_HEADS), 256, smem_bytes>>>();

    // Output projection -> d_out
    gemm_bias_kernel<0><<<ggrid, gblk>>>(gao, Wo, bo, out);
}

// round 2
// speedup vs baseline: 3.8821x; 3.8821x over previous
#include <cuda_runtime.h>
#include <math.h>

#define D_MODEL 1024
#define N_HEADS 16
#define DEPTH   64
#define BATCH   2
#define SEQ     2048
#define M_TOT   (BATCH * SEQ)   // 4096

// ---------------------------------------------------------------------------
// Scratch (no cudaMalloc allowed): device globals
// ---------------------------------------------------------------------------
__device__ float g_q[BATCH * N_HEADS * SEQ * DEPTH];   // [B,H,S,64]
__device__ float g_k[BATCH * N_HEADS * SEQ * DEPTH];
__device__ float g_v[BATCH * N_HEADS * SEQ * DEPTH];
__device__ float g_ao[M_TOT * D_MODEL];                // attention out [B,S,D]

// ---------------------------------------------------------------------------
// GEMM v2: Y = X @ W^T + bias.  X:[4096,1024], W:[1024,1024] (out-features rows)
// BM=BN=128, BK=16, 256 threads, 8x8 micro-tile.
// ---------------------------------------------------------------------------
#define GLDA 132   // smem leading dim (pad for STS conflicts)

template <int HEAD_SPLIT>
__global__ __launch_bounds__(256, 2)
void gemm_bias_kernel(const float* __restrict__ X,
                      const float* __restrict__ W,
                      const float* __restrict__ bias,
                      float* __restrict__ Y)
{
    __shared__ float As[16][GLDA];
    __shared__ float Bs[16][GLDA];

    const int tid = threadIdx.x;
    const int ty  = tid >> 4;      // 0..15
    const int tx  = tid & 15;      // 0..15
    const int m0  = blockIdx.y * 128;
    const int n0  = blockIdx.x * 128;

    float c[8][8];
    #pragma unroll
    for (int i = 0; i < 8; i++)
        #pragma unroll
        for (int j = 0; j < 8; j++) c[i][j] = 0.0f;

    for (int k0 = 0; k0 < D_MODEL; k0 += 16) {
        // Load 128x16 A and B tiles (2 float4 per thread each)
        #pragma unroll
        for (int i = 0; i < 2; i++) {
            int id  = tid + i * 256;    // 0..511
            int row = id >> 2;          // 0..127
            int k4  = id & 3;           // 0..3
            float4 a = *(const float4*)&X[(size_t)(m0 + row) * D_MODEL + k0 + k4 * 4];
            float4 b = *(const float4*)&W[(size_t)(n0 + row) * D_MODEL + k0 + k4 * 4];
            As[k4 * 4 + 0][row] = a.x;
            As[k4 * 4 + 1][row] = a.y;
            As[k4 * 4 + 2][row] = a.z;
            As[k4 * 4 + 3][row] = a.w;
            Bs[k4 * 4 + 0][row] = b.x;
            Bs[k4 * 4 + 1][row] = b.y;
            Bs[k4 * 4 + 2][row] = b.z;
            Bs[k4 * 4 + 3][row] = b.w;
        }
        __syncthreads();

        #pragma unroll
        for (int k = 0; k < 16; k++) {
            float4 a0 = *(float4*)&As[k][ty * 4];
            float4 a1 = *(float4*)&As[k][64 + ty * 4];
            float4 b0 = *(float4*)&Bs[k][tx * 4];
            float4 b1 = *(float4*)&Bs[k][64 + tx * 4];
            float av[8] = {a0.x, a0.y, a0.z, a0.w, a1.x, a1.y, a1.z, a1.w};
            float bv[8] = {b0.x, b0.y, b0.z, b0.w, b1.x, b1.y, b1.z, b1.w};
            #pragma unroll
            for (int i = 0; i < 8; i++)
                #pragma unroll
                for (int j = 0; j < 8; j++)
                    c[i][j] += av[i] * bv[j];
        }
        __syncthreads();
    }

    // Epilogue
    float4 bb0 = *(const float4*)&bias[n0 + tx * 4];
    float4 bb1 = *(const float4*)&bias[n0 + 64 + tx * 4];
    const float badd[8] = {bb0.x, bb0.y, bb0.z, bb0.w, bb1.x, bb1.y, bb1.z, bb1.w};

    #pragma unroll
    for (int i = 0; i < 8; i++) {
        const int m = m0 + ((i < 4) ? (ty * 4 + i) : (64 + ty * 4 + i - 4));
        #pragma unroll
        for (int jh = 0; jh < 2; jh++) {
            const int n = n0 + jh * 64 + tx * 4;
            float4 o;
            o.x = c[i][jh * 4 + 0] + badd[jh * 4 + 0];
            o.y = c[i][jh * 4 + 1] + badd[jh * 4 + 1];
            o.z = c[i][jh * 4 + 2] + badd[jh * 4 + 2];
            o.w = c[i][jh * 4 + 3] + badd[jh * 4 + 3];
            if (HEAD_SPLIT) {
                const int b  = m >> 11;
                const int s  = m & (SEQ - 1);
                const int h  = n >> 6;
                const int dd = n & 63;
                *(float4*)&Y[((size_t)(b * N_HEADS + h) * SEQ + s) * DEPTH + dd] = o;
            } else {
                *(float4*)&Y[(size_t)m * D_MODEL + n] = o;
            }
        }
    }
}

// ---------------------------------------------------------------------------
// Flash attention v2: BQ=128, BKV=64. 256 threads = 16x16 grid.
// Thread (ty,tx): q-rows 8ty..8ty+7, cols 4tx..4tx+3.
// Scores + softmax in registers; running m/l in registers; P via smem (k-major).
// ---------------------------------------------------------------------------
#define BQ  128
#define BKV 64
#define LDP 132   // p_t leading dim

__global__ __launch_bounds__(256, 2)
void flash_attn_kernel()
{
    extern __shared__ float sm[];
    float* q_t = sm;                        // [64][128]  d-major
    float* k_t = q_t + 64 * 128;            // [64][64]   d-major
    float* v_s = k_t + 64 * 64;             // [64][64]   row-major (k,d)
    float* p_t = v_s + 64 * 64;             // [64][LDP]  k-major (k, qrow)

    const int tid = threadIdx.x;
    const int ty  = tid >> 4;   // 0..15 (q-row group)
    const int tx  = tid & 15;   // 0..15 (col group)

    const int q0 = blockIdx.x * BQ;
    const int bh = blockIdx.y;
    const int b  = bh >> 4;
    const int h  = bh & 15;

    const float scale = 0.125f;   // 1/sqrt(64), folded into Q

    const float* gq = g_q + ((size_t)bh * SEQ + q0) * DEPTH;
    const float* gk = g_k + (size_t)bh * SEQ * DEPTH;
    const float* gv = g_v + (size_t)bh * SEQ * DEPTH;

    // Load Q tile transposed (scaled). 2048 f4 / 256 thr = 8 each.
    // row fast within warp -> conflict-free STS.
    #pragma unroll
    for (int i = 0; i < 8; i++) {
        int id  = tid + i * 256;     // 0..2047
        int row = id & 127;
        int d4  = id >> 7;           // 0..15
        float4 v = *(const float4*)&gq[row * DEPTH + d4 * 4];
        q_t[(d4 * 4 + 0) * 128 + row] = v.x * scale;
        q_t[(d4 * 4 + 1) * 128 + row] = v.y * scale;
        q_t[(d4 * 4 + 2) * 128 + row] = v.z * scale;
        q_t[(d4 * 4 + 3) * 128 + row] = v.w * scale;
    }

    float out[8][4];
    float m_run[8], l_run[8];
    #pragma unroll
    for (int i = 0; i < 8; i++) {
        m_run[i] = -INFINITY;
        l_run[i] = 0.0f;
        #pragma unroll
        for (int j = 0; j < 4; j++) out[i][j] = 0.0f;
    }

    for (int jc = 0; jc < SEQ / BKV; jc++) {
        __syncthreads();   // prev PV done before K/V overwrite

        const float* kp = gk + (size_t)jc * BKV * DEPTH;
        const float* vp = gv + (size_t)jc * BKV * DEPTH;
        // K transposed: 1024 f4 / 256 = 4 each, row fast in warp
        #pragma unroll
        for (int i = 0; i < 4; i++) {
            int id  = tid + i * 256;   // 0..1023
            int row = id & 63;
            int d4  = id >> 6;         // 0..15
            float4 v = *(const float4*)&kp[row * DEPTH + d4 * 4];
            k_t[(d4 * 4 + 0) * 64 + row] = v.x;
            k_t[(d4 * 4 + 1) * 64 + row] = v.y;
            k_t[(d4 * 4 + 2) * 64 + row] = v.z;
            k_t[(d4 * 4 + 3) * 64 + row] = v.w;
        }
        // V row-major straight copy (coalesced)
        #pragma unroll
        for (int i = 0; i < 4; i++) {
            int id  = tid + i * 256;
            int row = id >> 4;
            int d4  = id & 15;
            *(float4*)&v_s[row * 64 + d4 * 4] =
                *(const float4*)&vp[row * DEPTH + d4 * 4];
        }
        __syncthreads();

        // Scores: sacc[i][j] = sum_d q[8ty+i][d] * k[4tx+j][d]
        float sacc[8][4];
        #pragma unroll
        for (int i = 0; i < 8; i++)
            #pragma unroll
            for (int j = 0; j < 4; j++) sacc[i][j] = 0.0f;

        #pragma unroll 8
        for (int d = 0; d < 64; d++) {
            float4 qa = *(float4*)&q_t[d * 128 + 8 * ty];
            float4 qb = *(float4*)&q_t[d * 128 + 8 * ty + 4];
            float4 kk = *(float4*)&k_t[d * 64 + 4 * tx];
            float qv[8] = {qa.x, qa.y, qa.z, qa.w, qb.x, qb.y, qb.z, qb.w};
            float kv[4] = {kk.x, kk.y, kk.z, kk.w};
            #pragma unroll
            for (int i = 0; i < 8; i++)
                #pragma unroll
                for (int j = 0; j < 4; j++)
                    sacc[i][j] += qv[i] * kv[j];
        }

        // Online softmax in registers. Row stats via shfl over 16 lanes (tx bits).
        #pragma unroll
        for (int i = 0; i < 8; i++) {
            float mx = fmaxf(fmaxf(sacc[i][0], sacc[i][1]),
                             fmaxf(sacc[i][2], sacc[i][3]));
            mx = fmaxf(mx, __shfl_xor_sync(0xffffffffu, mx, 1));
            mx = fmaxf(mx, __shfl_xor_sync(0xffffffffu, mx, 2));
            mx = fmaxf(mx, __shfl_xor_sync(0xffffffffu, mx, 4));
            mx = fmaxf(mx, __shfl_xor_sync(0xffffffffu, mx, 8));
            float mnew  = fmaxf(m_run[i], mx);
            float alpha = __expf(m_run[i] - mnew);
            m_run[i] = mnew;
            float p0 = __expf(sacc[i][0] - mnew);
            float p1 = __expf(sacc[i][1] - mnew);
            float p2 = __expf(sacc[i][2] - mnew);
            float p3 = __expf(sacc[i][3] - mnew);
            sacc[i][0] = p0; sacc[i][1] = p1; sacc[i][2] = p2; sacc[i][3] = p3;
            float rs = (p0 + p1) + (p2 + p3);
            rs += __shfl_xor_sync(0xffffffffu, rs, 1);
            rs += __shfl_xor_sync(0xffffffffu, rs, 2);
            rs += __shfl_xor_sync(0xffffffffu, rs, 4);
            rs += __shfl_xor_sync(0xffffffffu, rs, 8);
            l_run[i] = l_run[i] * alpha + rs;
            out[i][0] *= alpha; out[i][1] *= alpha;
            out[i][2] *= alpha; out[i][3] *= alpha;
        }

        // Write P k-major: p_t[col][qrow]
        #pragma unroll
        for (int j = 0; j < 4; j++) {
            float4 pa = make_float4(sacc[0][j], sacc[1][j], sacc[2][j], sacc[3][j]);
            float4 pb = make_float4(sacc[4][j], sacc[5][j], sacc[6][j], sacc[7][j]);
            *(float4*)&p_t[(4 * tx + j) * LDP + 8 * ty]     = pa;
            *(float4*)&p_t[(4 * tx + j) * LDP + 8 * ty + 4] = pb;
        }
        __syncthreads();

        // PV: out[i][j] += sum_k p[8ty+i][k] * v[k][4tx+j]
        #pragma unroll 8
        for (int k = 0; k < 64; k++) {
            float4 pa = *(float4*)&p_t[k * LDP + 8 * ty];
            float4 pb = *(float4*)&p_t[k * LDP + 8 * ty + 4];
            float4 vv = *(float4*)&v_s[k * 64 + 4 * tx];
            float pv[8] = {pa.x, pa.y, pa.z, pa.w, pb.x, pb.y, pb.z, pb.w};
            float vj[4] = {vv.x, vv.y, vv.z, vv.w};
            #pragma unroll
            for (int i = 0; i < 8; i++)
                #pragma unroll
                for (int j = 0; j < 4; j++)
                    out[i][j] += pv[i] * vj[j];
        }
    }

    // Epilogue: normalize, write [B,S,D] with heads re-interleaved
    #pragma unroll
    for (int i = 0; i < 8; i++) {
        float inv = 1.0f / l_run[i];
        float4 o;
        o.x = out[i][0] * inv;
        o.y = out[i][1] * inv;
        o.z = out[i][2] * inv;
        o.w = out[i][3] * inv;
        *(float4*)&g_ao[((size_t)(b * SEQ + q0 + 8 * ty + i)) * D_MODEL
                        + h * DEPTH + 4 * tx] = o;
    }
}

// ---------------------------------------------------------------------------
// Launch
// ---------------------------------------------------------------------------
extern "C" void kernel_launch(void* const* d_in, const int* in_sizes, int n_in,
                              void* d_out, int out_size)
{
    const float* Q  = (const float*)d_in[0];
    const float* K  = (const float*)d_in[1];
    const float* V  = (const float*)d_in[2];
    const float* Wq = (const float*)d_in[3];
    const float* bq = (const float*)d_in[4];
    const float* Wk = (const float*)d_in[5];
    const float* bk = (const float*)d_in[6];
    const float* Wv = (const float*)d_in[7];
    const float* bv = (const float*)d_in[8];
    const float* Wo = (const float*)d_in[9];
    const float* bo = (const float*)d_in[10];
    float* out = (float*)d_out;

    float *gq, *gk, *gv, *gao;
    cudaGetSymbolAddress((void**)&gq,  g_q);
    cudaGetSymbolAddress((void**)&gk,  g_k);
    cudaGetSymbolAddress((void**)&gv,  g_v);
    cudaGetSymbolAddress((void**)&gao, g_ao);

    const dim3 ggrid(D_MODEL / 128, M_TOT / 128);   // (8, 32)
    const dim3 gblk(256);

    gemm_bias_kernel<1><<<ggrid, gblk>>>(Q, Wq, bq, gq);
    gemm_bias_kernel<1><<<ggrid, gblk>>>(K, Wk, bk, gk);
    gemm_bias_kernel<1><<<ggrid, gblk>>>(V, Wv, bv, gv);

    const int smem_bytes = (64 * 128 + 64 * 64 + 64 * 64 + 64 * LDP) * (int)sizeof(float);
    static bool attr_set = false;
    if (!attr_set) {
        cudaFuncSetAttribute(flash_attn_kernel,
                             cudaFuncAttributeMaxDynamicSharedMemorySize, smem_bytes);
        attr_set = true;
    }
    flash_attn_kernel<<<dim3(SEQ / BQ, BATCH * N_HEADS), 256, smem_bytes>>>();

    gemm_bias_kernel<0><<<ggrid, gblk>>>(gao, Wo, bo, out);
}

// round 5
// speedup vs baseline: 5.5824x; 1.4380x over previous
#include <cuda_runtime.h>
#include <math.h>
#include <stdint.h>

#define D_MODEL 1024
#define N_HEADS 16
#define DEPTH   64
#define BATCH   2
#define SEQ     2048
#define M_TOT   (BATCH * SEQ)   // 4096

// ---------------------------------------------------------------------------
// Scratch (no cudaMalloc allowed): device globals
// ---------------------------------------------------------------------------
__device__ float g_q[BATCH * N_HEADS * SEQ * DEPTH];   // [B,H,S,64]
__device__ float g_k[BATCH * N_HEADS * SEQ * DEPTH];
__device__ float g_v[BATCH * N_HEADS * SEQ * DEPTH];
__device__ float g_ao[M_TOT * D_MODEL];                // attention out [B,S,D]

// ---------------------------------------------------------------------------
// mma.sync tf32 helpers (baseline PTX, valid on sm_103 target)
// ---------------------------------------------------------------------------
__device__ __forceinline__ void mma_tf32(float c[4], const uint32_t a[4],
                                         const uint32_t b[2]) {
    asm volatile(
        "mma.sync.aligned.m16n8k8.row.col.f32.tf32.tf32.f32 "
        "{%0,%1,%2,%3}, {%4,%5,%6,%7}, {%8,%9}, {%0,%1,%2,%3};\n"
        : "+f"(c[0]), "+f"(c[1]), "+f"(c[2]), "+f"(c[3])
        : "r"(a[0]), "r"(a[1]), "r"(a[2]), "r"(a[3]),
          "r"(b[0]), "r"(b[1]));
}

__device__ __forceinline__ float tf32_round(float x) {
    uint32_t t;
    asm("cvt.rna.tf32.f32 %0, %1;" : "=r"(t) : "f"(x));
    return __uint_as_float(t);
}

// ---------------------------------------------------------------------------
// GEMM (tensor-core tf32): Y = X @ W^T + bias
// X:[4096,1024], W:[1024,1024] row-major (torch Linear weight: out-features rows).
// Block 128x128, BK=16, double-buffered smem, 256 threads = 8 warps (2m x 4n),
// warp tile 64x32 -> 4 m-frags x 4 n-frags of m16n8k8.
// Smem rows padded to 20 floats: fragment scalar LDS conflict-free
// (20g+t mod 32 is a bank permutation), staging STS.128 conflict-free.
// ---------------------------------------------------------------------------
#define BK   16
#define LDA  20
#define STAGEF (128 * LDA)   // 2560 floats per operand per stage

template <int HEAD_SPLIT>
__global__ __launch_bounds__(256, 2)
void gemm_mma_kernel(const float* __restrict__ X,
                     const float* __restrict__ W,
                     const float* __restrict__ bias,
                     float* __restrict__ Y)
{
    __shared__ float sA[2][STAGEF];
    __shared__ float sB[2][STAGEF];

    const int tid  = threadIdx.x;
    const int lane = tid & 31;
    const int wid  = tid >> 5;
    const int wm   = wid & 1;     // 0..1  (m warp)
    const int wn   = wid >> 1;    // 0..3  (n warp)
    const int g    = lane >> 2;   // 0..7
    const int t    = lane & 3;    // 0..3
    const int m0   = blockIdx.y * 128;
    const int n0   = blockIdx.x * 128;

    const int lrow = tid >> 2;    // 0..63 (loader row base)
    const int lkq  = tid & 3;     // 0..3  (loader float4 within 16-float row)

    float cacc[4][4][4];
    #pragma unroll
    for (int mf = 0; mf < 4; mf++)
        #pragma unroll
        for (int nf = 0; nf < 4; nf++)
            #pragma unroll
            for (int r = 0; r < 4; r++) cacc[mf][nf][r] = 0.0f;

    const float* Xb = X + (size_t)m0 * D_MODEL;
    const float* Wb = W + (size_t)n0 * D_MODEL;

    float4 ra[2], rb[2];

    // Prologue: load chunk 0
    #pragma unroll
    for (int j = 0; j < 2; j++) {
        ra[j] = *(const float4*)(Xb + (size_t)(lrow + j * 64) * D_MODEL + lkq * 4);
        rb[j] = *(const float4*)(Wb + (size_t)(lrow + j * 64) * D_MODEL + lkq * 4);
    }
    #pragma unroll
    for (int j = 0; j < 2; j++) {
        const int row = lrow + j * 64;
        float4 a = ra[j], b = rb[j];
        a.x = tf32_round(a.x); a.y = tf32_round(a.y);
        a.z = tf32_round(a.z); a.w = tf32_round(a.w);
        b.x = tf32_round(b.x); b.y = tf32_round(b.y);
        b.z = tf32_round(b.z); b.w = tf32_round(b.w);
        *(float4*)&sA[0][row * LDA + lkq * 4] = a;
        *(float4*)&sB[0][row * LDA + lkq * 4] = b;
    }
    __syncthreads();

    const int NCH = D_MODEL / BK;   // 64
    for (int c = 0; c < NCH; c++) {
        const int p = c & 1;
        if (c + 1 < NCH) {
            const int koff = (c + 1) * BK;
            #pragma unroll
            for (int j = 0; j < 2; j++) {
                ra[j] = *(const float4*)(Xb + (size_t)(lrow + j * 64) * D_MODEL + koff + lkq * 4);
                rb[j] = *(const float4*)(Wb + (size_t)(lrow + j * 64) * D_MODEL + koff + lkq * 4);
            }
        }

        // Compute stage p: 2 k-steps of 8
        #pragma unroll
        for (int ks = 0; ks < 2; ks++) {
            const int kb = ks * 8 + t;
            uint32_t af[4][4], bf[4][2];
            #pragma unroll
            for (int mf = 0; mf < 4; mf++) {
                const int rm = wm * 64 + mf * 16 + g;
                af[mf][0] = __float_as_uint(sA[p][rm * LDA + kb]);
                af[mf][1] = __float_as_uint(sA[p][(rm + 8) * LDA + kb]);
                af[mf][2] = __float_as_uint(sA[p][rm * LDA + kb + 4]);
                af[mf][3] = __float_as_uint(sA[p][(rm + 8) * LDA + kb + 4]);
            }
            #pragma unroll
            for (int nf = 0; nf < 4; nf++) {
                const int cn = wn * 32 + nf * 8 + g;
                bf[nf][0] = __float_as_uint(sB[p][cn * LDA + kb]);
                bf[nf][1] = __float_as_uint(sB[p][cn * LDA + kb + 4]);
            }
            #pragma unroll
            for (int mf = 0; mf < 4; mf++)
                #pragma unroll
                for (int nf = 0; nf < 4; nf++)
                    mma_tf32(cacc[mf][nf], af[mf], bf[nf]);
        }

        if (c + 1 < NCH) {
            const int q = p ^ 1;
            #pragma unroll
            for (int j = 0; j < 2; j++) {
                const int row = lrow + j * 64;
                float4 a = ra[j], b = rb[j];
                a.x = tf32_round(a.x); a.y = tf32_round(a.y);
                a.z = tf32_round(a.z); a.w = tf32_round(a.w);
                b.x = tf32_round(b.x); b.y = tf32_round(b.y);
                b.z = tf32_round(b.z); b.w = tf32_round(b.w);
                *(float4*)&sA[q][row * LDA + lkq * 4] = a;
                *(float4*)&sB[q][row * LDA + lkq * 4] = b;
            }
            __syncthreads();
        }
    }

    // Epilogue: add bias, store. C frag: c0=(g,2t) c1=(g,2t+1) c2=(g+8,2t) c3=(g+8,2t+1)
    #pragma unroll
    for (int mf = 0; mf < 4; mf++) {
        #pragma unroll
        for (int nf = 0; nf < 4; nf++) {
            const int m = m0 + wm * 64 + mf * 16 + g;
            const int n = n0 + wn * 32 + nf * 8 + 2 * t;
            float2 bb = *(const float2*)&bias[n];
            float2 r0, r1;
            r0.x = cacc[mf][nf][0] + bb.x;
            r0.y = cacc[mf][nf][1] + bb.y;
            r1.x = cacc[mf][nf][2] + bb.x;
            r1.y = cacc[mf][nf][3] + bb.y;
            if (HEAD_SPLIT) {
                const int h  = n >> 6;
                const int dd = n & 63;
                const int b1 = m >> 11;
                const int s1 = m & (SEQ - 1);
                *(float2*)&Y[((size_t)(b1 * N_HEADS + h) * SEQ + s1) * DEPTH + dd] = r0;
                const int m2 = m + 8;
                const int b2 = m2 >> 11;
                const int s2 = m2 & (SEQ - 1);
                *(float2*)&Y[((size_t)(b2 * N_HEADS + h) * SEQ + s2) * DEPTH + dd] = r1;
            } else {
                *(float2*)&Y[(size_t)m * D_MODEL + n] = r0;
                *(float2*)&Y[(size_t)(m + 8) * D_MODEL + n] = r1;
            }
        }
    }
}

// ---------------------------------------------------------------------------
// Flash attention (R2 version, fp32 SIMT — known good at 894us)
// ---------------------------------------------------------------------------
#define BQ  128
#define BKV 64
#define LDP 132

__global__ __launch_bounds__(256, 2)
void flash_attn_kernel()
{
    extern __shared__ float sm[];
    float* q_t = sm;                        // [64][128]  d-major
    float* k_t = q_t + 64 * 128;            // [64][64]   d-major
    float* v_s = k_t + 64 * 64;             // [64][64]   row-major
    float* p_t = v_s + 64 * 64;             // [64][LDP]  k-major

    const int tid = threadIdx.x;
    const int ty  = tid >> 4;
    const int tx  = tid & 15;

    const int q0 = blockIdx.x * BQ;
    const int bh = blockIdx.y;
    const int b  = bh >> 4;
    const int h  = bh & 15;

    const float scale = 0.125f;

    const float* gq = g_q + ((size_t)bh * SEQ + q0) * DEPTH;
    const float* gk = g_k + (size_t)bh * SEQ * DEPTH;
    const float* gv = g_v + (size_t)bh * SEQ * DEPTH;

    #pragma unroll
    for (int i = 0; i < 8; i++) {
        int id  = tid + i * 256;
        int row = id & 127;
        int d4  = id >> 7;
        float4 v = *(const float4*)&gq[row * DEPTH + d4 * 4];
        q_t[(d4 * 4 + 0) * 128 + row] = v.x * scale;
        q_t[(d4 * 4 + 1) * 128 + row] = v.y * scale;
        q_t[(d4 * 4 + 2) * 128 + row] = v.z * scale;
        q_t[(d4 * 4 + 3) * 128 + row] = v.w * scale;
    }

    float out[8][4];
    float m_run[8], l_run[8];
    #pragma unroll
    for (int i = 0; i < 8; i++) {
        m_run[i] = -INFINITY;
        l_run[i] = 0.0f;
        #pragma unroll
        for (int j = 0; j < 4; j++) out[i][j] = 0.0f;
    }

    for (int jc = 0; jc < SEQ / BKV; jc++) {
        __syncthreads();

        const float* kp = gk + (size_t)jc * BKV * DEPTH;
        const float* vp = gv + (size_t)jc * BKV * DEPTH;
        #pragma unroll
        for (int i = 0; i < 4; i++) {
            int id  = tid + i * 256;
            int row = id & 63;
            int d4  = id >> 6;
            float4 v = *(const float4*)&kp[row * DEPTH + d4 * 4];
            k_t[(d4 * 4 + 0) * 64 + row] = v.x;
            k_t[(d4 * 4 + 1) * 64 + row] = v.y;
            k_t[(d4 * 4 + 2) * 64 + row] = v.z;
            k_t[(d4 * 4 + 3) * 64 + row] = v.w;
        }
        #pragma unroll
        for (int i = 0; i < 4; i++) {
            int id  = tid + i * 256;
            int row = id >> 4;
            int d4  = id & 15;
            *(float4*)&v_s[row * 64 + d4 * 4] =
                *(const float4*)&vp[row * DEPTH + d4 * 4];
        }
        __syncthreads();

        float sacc[8][4];
        #pragma unroll
        for (int i = 0; i < 8; i++)
            #pragma unroll
            for (int j = 0; j < 4; j++) sacc[i][j] = 0.0f;

        #pragma unroll 8
        for (int d = 0; d < 64; d++) {
            float4 qa = *(float4*)&q_t[d * 128 + 8 * ty];
            float4 qb = *(float4*)&q_t[d * 128 + 8 * ty + 4];
            float4 kk = *(float4*)&k_t[d * 64 + 4 * tx];
            float qv[8] = {qa.x, qa.y, qa.z, qa.w, qb.x, qb.y, qb.z, qb.w};
            float kv[4] = {kk.x, kk.y, kk.z, kk.w};
            #pragma unroll
            for (int i = 0; i < 8; i++)
                #pragma unroll
                for (int j = 0; j < 4; j++)
                    sacc[i][j] += qv[i] * kv[j];
        }

        #pragma unroll
        for (int i = 0; i < 8; i++) {
            float mx = fmaxf(fmaxf(sacc[i][0], sacc[i][1]),
                             fmaxf(sacc[i][2], sacc[i][3]));
            mx = fmaxf(mx, __shfl_xor_sync(0xffffffffu, mx, 1));
            mx = fmaxf(mx, __shfl_xor_sync(0xffffffffu, mx, 2));
            mx = fmaxf(mx, __shfl_xor_sync(0xffffffffu, mx, 4));
            mx = fmaxf(mx, __shfl_xor_sync(0xffffffffu, mx, 8));
            float mnew  = fmaxf(m_run[i], mx);
            float alpha = __expf(m_run[i] - mnew);
            m_run[i] = mnew;
            float p0 = __expf(sacc[i][0] - mnew);
            float p1 = __expf(sacc[i][1] - mnew);
            float p2 = __expf(sacc[i][2] - mnew);
            float p3 = __expf(sacc[i][3] - mnew);
            sacc[i][0] = p0; sacc[i][1] = p1; sacc[i][2] = p2; sacc[i][3] = p3;
            float rs = (p0 + p1) + (p2 + p3);
            rs += __shfl_xor_sync(0xffffffffu, rs, 1);
            rs += __shfl_xor_sync(0xffffffffu, rs, 2);
            rs += __shfl_xor_sync(0xffffffffu, rs, 4);
            rs += __shfl_xor_sync(0xffffffffu, rs, 8);
            l_run[i] = l_run[i] * alpha + rs;
            out[i][0] *= alpha; out[i][1] *= alpha;
            out[i][2] *= alpha; out[i][3] *= alpha;
        }

        #pragma unroll
        for (int j = 0; j < 4; j++) {
            float4 pa = make_float4(sacc[0][j], sacc[1][j], sacc[2][j], sacc[3][j]);
            float4 pb = make_float4(sacc[4][j], sacc[5][j], sacc[6][j], sacc[7][j]);
            *(float4*)&p_t[(4 * tx + j) * LDP + 8 * ty]     = pa;
            *(float4*)&p_t[(4 * tx + j) * LDP + 8 * ty + 4] = pb;
        }
        __syncthreads();

        #pragma unroll 8
        for (int k = 0; k < 64; k++) {
            float4 pa = *(float4*)&p_t[k * LDP + 8 * ty];
            float4 pb = *(float4*)&p_t[k * LDP + 8 * ty + 4];
            float4 vv = *(float4*)&v_s[k * 64 + 4 * tx];
            float pv[8] = {pa.x, pa.y, pa.z, pa.w, pb.x, pb.y, pb.z, pb.w};
            float vj[4] = {vv.x, vv.y, vv.z, vv.w};
            #pragma unroll
            for (int i = 0; i < 8; i++)
                #pragma unroll
                for (int j = 0; j < 4; j++)
                    out[i][j] += pv[i] * vj[j];
        }
    }

    #pragma unroll
    for (int i = 0; i < 8; i++) {
        float inv = 1.0f / l_run[i];
        float4 o;
        o.x = out[i][0] * inv;
        o.y = out[i][1] * inv;
        o.z = out[i][2] * inv;
        o.w = out[i][3] * inv;
        *(float4*)&g_ao[((size_t)(b * SEQ + q0 + 8 * ty + i)) * D_MODEL
                        + h * DEPTH + 4 * tx] = o;
    }
}

// ---------------------------------------------------------------------------
// Launch
// ---------------------------------------------------------------------------
extern "C" void kernel_launch(void* const* d_in, const int* in_sizes, int n_in,
                              void* d_out, int out_size)
{
    const float* Q  = (const float*)d_in[0];
    const float* K  = (const float*)d_in[1];
    const float* V  = (const float*)d_in[2];
    const float* Wq = (const float*)d_in[3];
    const float* bq = (const float*)d_in[4];
    const float* Wk = (const float*)d_in[5];
    const float* bk = (const float*)d_in[6];
    const float* Wv = (const float*)d_in[7];
    const float* bv = (const float*)d_in[8];
    const float* Wo = (const float*)d_in[9];
    const float* bo = (const float*)d_in[10];
    float* out = (float*)d_out;

    float *gq, *gk, *gv, *gao;
    cudaGetSymbolAddress((void**)&gq,  g_q);
    cudaGetSymbolAddress((void**)&gk,  g_k);
    cudaGetSymbolAddress((void**)&gv,  g_v);
    cudaGetSymbolAddress((void**)&gao, g_ao);

    const int flash_smem = (64 * 128 + 64 * 64 + 64 * 64 + 64 * LDP) * (int)sizeof(float);
    static bool attr_set = false;
    if (!attr_set) {
        cudaFuncSetAttribute(flash_attn_kernel,
                             cudaFuncAttributeMaxDynamicSharedMemorySize, flash_smem);
        attr_set = true;
    }

    const dim3 ggrid(D_MODEL / 128, M_TOT / 128);   // (8, 32)

    // Q/K/V projections (mma.sync tf32) -> head-split scratch
    gemm_mma_kernel<1><<<ggrid, 256>>>(Q, Wq, bq, gq);
    gemm_mma_kernel<1><<<ggrid, 256>>>(K, Wk, bk, gk);
    gemm_mma_kernel<1><<<ggrid, 256>>>(V, Wv, bv, gv);

    // Flash attention (fp32 SIMT)
    flash_attn_kernel<<<dim3(SEQ / BQ, BATCH * N_HEADS), 256, flash_smem>>>();

    // Output projection (mma.sync tf32) -> d_out
    gemm_mma_kernel<0><<<ggrid, 256>>>(gao, Wo, bo, out);
}

// round 6
// speedup vs baseline: 10.9488x; 1.9613x over previous
#include <cuda_runtime.h>
#include <math.h>
#include <stdint.h>

#define D_MODEL 1024
#define N_HEADS 16
#define DEPTH   64
#define BATCH   2
#define SEQ     2048
#define M_TOT   (BATCH * SEQ)   // 4096

// ---------------------------------------------------------------------------
// Scratch (no cudaMalloc allowed): device globals
// ---------------------------------------------------------------------------
__device__ float g_q[BATCH * N_HEADS * SEQ * DEPTH];   // [B,H,S,64]
__device__ float g_k[BATCH * N_HEADS * SEQ * DEPTH];
__device__ float g_v[BATCH * N_HEADS * SEQ * DEPTH];
__device__ float g_ao[M_TOT * D_MODEL];                // attention out [B,S,D]

// ---------------------------------------------------------------------------
// mma.sync tf32 helpers (baseline PTX, valid on sm_103 target)
// ---------------------------------------------------------------------------
__device__ __forceinline__ void mma_tf32(float c[4], const uint32_t a[4],
                                         const uint32_t b[2]) {
    asm volatile(
        "mma.sync.aligned.m16n8k8.row.col.f32.tf32.tf32.f32 "
        "{%0,%1,%2,%3}, {%4,%5,%6,%7}, {%8,%9}, {%0,%1,%2,%3};\n"
        : "+f"(c[0]), "+f"(c[1]), "+f"(c[2]), "+f"(c[3])
        : "r"(a[0]), "r"(a[1]), "r"(a[2]), "r"(a[3]),
          "r"(b[0]), "r"(b[1]));
}

__device__ __forceinline__ float tf32_round(float x) {
    uint32_t t;
    asm("cvt.rna.tf32.f32 %0, %1;" : "=r"(t) : "f"(x));
    return __uint_as_float(t);
}

// ---------------------------------------------------------------------------
// GEMM (tensor-core tf32): Y = X @ W^T + bias   (unchanged from R5, passing)
// ---------------------------------------------------------------------------
#define BK   16
#define LDA  20
#define STAGEF (128 * LDA)

template <int HEAD_SPLIT>
__global__ __launch_bounds__(256, 2)
void gemm_mma_kernel(const float* __restrict__ X,
                     const float* __restrict__ W,
                     const float* __restrict__ bias,
                     float* __restrict__ Y)
{
    __shared__ float sA[2][STAGEF];
    __shared__ float sB[2][STAGEF];

    const int tid  = threadIdx.x;
    const int lane = tid & 31;
    const int wid  = tid >> 5;
    const int wm   = wid & 1;
    const int wn   = wid >> 1;
    const int g    = lane >> 2;
    const int t    = lane & 3;
    const int m0   = blockIdx.y * 128;
    const int n0   = blockIdx.x * 128;

    const int lrow = tid >> 2;
    const int lkq  = tid & 3;

    float cacc[4][4][4];
    #pragma unroll
    for (int mf = 0; mf < 4; mf++)
        #pragma unroll
        for (int nf = 0; nf < 4; nf++)
            #pragma unroll
            for (int r = 0; r < 4; r++) cacc[mf][nf][r] = 0.0f;

    const float* Xb = X + (size_t)m0 * D_MODEL;
    const float* Wb = W + (size_t)n0 * D_MODEL;

    float4 ra[2], rb[2];

    #pragma unroll
    for (int j = 0; j < 2; j++) {
        ra[j] = *(const float4*)(Xb + (size_t)(lrow + j * 64) * D_MODEL + lkq * 4);
        rb[j] = *(const float4*)(Wb + (size_t)(lrow + j * 64) * D_MODEL + lkq * 4);
    }
    #pragma unroll
    for (int j = 0; j < 2; j++) {
        const int row = lrow + j * 64;
        float4 a = ra[j], b = rb[j];
        a.x = tf32_round(a.x); a.y = tf32_round(a.y);
        a.z = tf32_round(a.z); a.w = tf32_round(a.w);
        b.x = tf32_round(b.x); b.y = tf32_round(b.y);
        b.z = tf32_round(b.z); b.w = tf32_round(b.w);
        *(float4*)&sA[0][row * LDA + lkq * 4] = a;
        *(float4*)&sB[0][row * LDA + lkq * 4] = b;
    }
    __syncthreads();

    const int NCH = D_MODEL / BK;
    for (int c = 0; c < NCH; c++) {
        const int p = c & 1;
        if (c + 1 < NCH) {
            const int koff = (c + 1) * BK;
            #pragma unroll
            for (int j = 0; j < 2; j++) {
                ra[j] = *(const float4*)(Xb + (size_t)(lrow + j * 64) * D_MODEL + koff + lkq * 4);
                rb[j] = *(const float4*)(Wb + (size_t)(lrow + j * 64) * D_MODEL + koff + lkq * 4);
            }
        }

        #pragma unroll
        for (int ks = 0; ks < 2; ks++) {
            const int kb = ks * 8 + t;
            uint32_t af[4][4], bf[4][2];
            #pragma unroll
            for (int mf = 0; mf < 4; mf++) {
                const int rm = wm * 64 + mf * 16 + g;
                af[mf][0] = __float_as_uint(sA[p][rm * LDA + kb]);
                af[mf][1] = __float_as_uint(sA[p][(rm + 8) * LDA + kb]);
                af[mf][2] = __float_as_uint(sA[p][rm * LDA + kb + 4]);
                af[mf][3] = __float_as_uint(sA[p][(rm + 8) * LDA + kb + 4]);
            }
            #pragma unroll
            for (int nf = 0; nf < 4; nf++) {
                const int cn = wn * 32 + nf * 8 + g;
                bf[nf][0] = __float_as_uint(sB[p][cn * LDA + kb]);
                bf[nf][1] = __float_as_uint(sB[p][cn * LDA + kb + 4]);
            }
            #pragma unroll
            for (int mf = 0; mf < 4; mf++)
                #pragma unroll
                for (int nf = 0; nf < 4; nf++)
                    mma_tf32(cacc[mf][nf], af[mf], bf[nf]);
        }

        if (c + 1 < NCH) {
            const int q = p ^ 1;
            #pragma unroll
            for (int j = 0; j < 2; j++) {
                const int row = lrow + j * 64;
                float4 a = ra[j], b = rb[j];
                a.x = tf32_round(a.x); a.y = tf32_round(a.y);
                a.z = tf32_round(a.z); a.w = tf32_round(a.w);
                b.x = tf32_round(b.x); b.y = tf32_round(b.y);
                b.z = tf32_round(b.z); b.w = tf32_round(b.w);
                *(float4*)&sA[q][row * LDA + lkq * 4] = a;
                *(float4*)&sB[q][row * LDA + lkq * 4] = b;
            }
            __syncthreads();
        }
    }

    #pragma unroll
    for (int mf = 0; mf < 4; mf++) {
        #pragma unroll
        for (int nf = 0; nf < 4; nf++) {
            const int m = m0 + wm * 64 + mf * 16 + g;
            const int n = n0 + wn * 32 + nf * 8 + 2 * t;
            float2 bb = *(const float2*)&bias[n];
            float2 r0, r1;
            r0.x = cacc[mf][nf][0] + bb.x;
            r0.y = cacc[mf][nf][1] + bb.y;
            r1.x = cacc[mf][nf][2] + bb.x;
            r1.y = cacc[mf][nf][3] + bb.y;
            if (HEAD_SPLIT) {
                const int h  = n >> 6;
                const int dd = n & 63;
                const int b1 = m >> 11;
                const int s1 = m & (SEQ - 1);
                *(float2*)&Y[((size_t)(b1 * N_HEADS + h) * SEQ + s1) * DEPTH + dd] = r0;
                const int m2 = m + 8;
                const int b2 = m2 >> 11;
                const int s2 = m2 & (SEQ - 1);
                *(float2*)&Y[((size_t)(b2 * N_HEADS + h) * SEQ + s2) * DEPTH + dd] = r1;
            } else {
                *(float2*)&Y[(size_t)m * D_MODEL + n] = r0;
                *(float2*)&Y[(size_t)(m + 8) * D_MODEL + n] = r1;
            }
        }
    }
}

// ---------------------------------------------------------------------------
// Flash attention via mma.sync tf32.
// 8 warps; warp w owns q-rows [16w, 16w+16). BQ=128, BKV=64, DEPTH=64.
// QK: A=Q frags (registers, loaded once), B=K (smem LD 68). S frags in regs.
// Softmax on frags (each thread holds 2 rows x 16 cols; shfl over t-lanes).
// P: tf32-rounded, staged in smem (reuses Q buffer, LD 68), __syncwarp only.
// PV: A=P (smem), B=V (smem LD 72). O accum in regs.
// Pads: LD68 == 4 mod 32 -> bank 4g+t (perm); LD72 == 8 mod 32 -> 8t+g (perm).
// ---------------------------------------------------------------------------
#define LDQ 68
#define LDK 68
#define LDV 72
#define FL_SMEM ((128 * LDQ + 64 * LDK + 64 * LDV) * 4)   // 70656 B

__global__ __launch_bounds__(256, 2)
void flash_mma_kernel()
{
    extern __shared__ float sm[];
    float* qp_s = sm;                   // [128][LDQ]: Q, then reused for P
    float* k_s  = qp_s + 128 * LDQ;     // [64][LDK]
    float* v_s  = k_s + 64 * LDK;       // [64][LDV]

    const int tid  = threadIdx.x;
    const int lane = tid & 31;
    const int w    = tid >> 5;     // warp id, q-row block
    const int g    = lane >> 2;    // 0..7
    const int t    = lane & 3;     // 0..3

    const int q0 = blockIdx.x * 128;
    const int bh = blockIdx.y;
    const int b  = bh >> 4;
    const int h  = bh & 15;

    const float scale = 0.125f;    // 1/sqrt(64), folded into Q

    const float* gq = g_q + ((size_t)bh * SEQ + q0) * DEPTH;
    const float* gk = g_k + (size_t)bh * SEQ * DEPTH;
    const float* gv = g_v + (size_t)bh * SEQ * DEPTH;

    // Load Q tile (scaled + tf32-rounded): 128x64 floats, 8 float4/thread
    #pragma unroll
    for (int i = 0; i < 8; i++) {
        int id   = tid + i * 256;     // 0..2047
        int row  = id >> 4;
        int col4 = id & 15;
        float4 v = *(const float4*)&gq[row * DEPTH + col4 * 4];
        v.x = tf32_round(v.x * scale);
        v.y = tf32_round(v.y * scale);
        v.z = tf32_round(v.z * scale);
        v.w = tf32_round(v.w * scale);
        *(float4*)&qp_s[row * LDQ + col4 * 4] = v;
    }
    __syncthreads();

    // Preload Q A-fragments for all 8 k-steps (32 regs), then Q smem is free
    const int mr0 = w * 16 + g;
    const int mr1 = mr0 + 8;
    uint32_t qf[8][4];
    #pragma unroll
    for (int ks = 0; ks < 8; ks++) {
        qf[ks][0] = __float_as_uint(qp_s[mr0 * LDQ + t + ks * 8]);
        qf[ks][1] = __float_as_uint(qp_s[mr1 * LDQ + t + ks * 8]);
        qf[ks][2] = __float_as_uint(qp_s[mr0 * LDQ + t + 4 + ks * 8]);
        qf[ks][3] = __float_as_uint(qp_s[mr1 * LDQ + t + 4 + ks * 8]);
    }

    float of[8][4];
    #pragma unroll
    for (int nf = 0; nf < 8; nf++)
        #pragma unroll
        for (int r = 0; r < 4; r++) of[nf][r] = 0.0f;
    float m0r = -INFINITY, m1r = -INFINITY;
    float l0r = 0.0f, l1r = 0.0f;

    for (int jc = 0; jc < SEQ / 64; jc++) {
        __syncthreads();   // prior PV reads of v_s / frag loads of qp_s done

        // Load K, V chunks (tf32-rounded): 64x64 each, 4 float4/thread each
        const float* kp = gk + (size_t)jc * 64 * DEPTH;
        const float* vp = gv + (size_t)jc * 64 * DEPTH;
        #pragma unroll
        for (int i = 0; i < 4; i++) {
            int id   = tid + i * 256;   // 0..1023
            int row  = id >> 4;
            int col4 = id & 15;
            float4 kv4 = *(const float4*)&kp[row * DEPTH + col4 * 4];
            kv4.x = tf32_round(kv4.x); kv4.y = tf32_round(kv4.y);
            kv4.z = tf32_round(kv4.z); kv4.w = tf32_round(kv4.w);
            *(float4*)&k_s[row * LDK + col4 * 4] = kv4;
            float4 vv4 = *(const float4*)&vp[row * DEPTH + col4 * 4];
            vv4.x = tf32_round(vv4.x); vv4.y = tf32_round(vv4.y);
            vv4.z = tf32_round(vv4.z); vv4.w = tf32_round(vv4.w);
            *(float4*)&v_s[row * LDV + col4 * 4] = vv4;
        }
        __syncthreads();

        // QK: S[128x64] -> per-warp m16 x n64 (8 n-frags), 8 k-steps
        float sf[8][4];
        #pragma unroll
        for (int nf = 0; nf < 8; nf++)
            #pragma unroll
            for (int r = 0; r < 4; r++) sf[nf][r] = 0.0f;

        #pragma unroll
        for (int ks = 0; ks < 8; ks++) {
            #pragma unroll
            for (int nf = 0; nf < 8; nf++) {
                uint32_t bf[2];
                bf[0] = __float_as_uint(k_s[(g + nf * 8) * LDK + t + ks * 8]);
                bf[1] = __float_as_uint(k_s[(g + nf * 8) * LDK + t + 4 + ks * 8]);
                mma_tf32(sf[nf], qf[ks], bf);
            }
        }

        // Online softmax on fragments. Thread rows: mr0 (c0,c1), mr1 (c2,c3).
        float mx0 = -INFINITY, mx1 = -INFINITY;
        #pragma unroll
        for (int nf = 0; nf < 8; nf++) {
            mx0 = fmaxf(mx0, fmaxf(sf[nf][0], sf[nf][1]));
            mx1 = fmaxf(mx1, fmaxf(sf[nf][2], sf[nf][3]));
        }
        mx0 = fmaxf(mx0, __shfl_xor_sync(0xffffffffu, mx0, 1));
        mx0 = fmaxf(mx0, __shfl_xor_sync(0xffffffffu, mx0, 2));
        mx1 = fmaxf(mx1, __shfl_xor_sync(0xffffffffu, mx1, 1));
        mx1 = fmaxf(mx1, __shfl_xor_sync(0xffffffffu, mx1, 2));

        const float mn0 = fmaxf(m0r, mx0);
        const float mn1 = fmaxf(m1r, mx1);
        const float al0 = __expf(m0r - mn0);
        const float al1 = __expf(m1r - mn1);
        m0r = mn0; m1r = mn1;

        // exp, round to tf32 (consistent numerator/denominator), row sums
        float rs0 = 0.0f, rs1 = 0.0f;
        #pragma unroll
        for (int nf = 0; nf < 8; nf++) {
            sf[nf][0] = tf32_round(__expf(sf[nf][0] - mn0));
            sf[nf][1] = tf32_round(__expf(sf[nf][1] - mn0));
            sf[nf][2] = tf32_round(__expf(sf[nf][2] - mn1));
            sf[nf][3] = tf32_round(__expf(sf[nf][3] - mn1));
            rs0 += sf[nf][0] + sf[nf][1];
            rs1 += sf[nf][2] + sf[nf][3];
        }
        rs0 += __shfl_xor_sync(0xffffffffu, rs0, 1);
        rs0 += __shfl_xor_sync(0xffffffffu, rs0, 2);
        rs1 += __shfl_xor_sync(0xffffffffu, rs1, 1);
        rs1 += __shfl_xor_sync(0xffffffffu, rs1, 2);
        l0r = l0r * al0 + rs0;
        l1r = l1r * al1 + rs1;

        // Rescale O accumulators
        #pragma unroll
        for (int nf = 0; nf < 8; nf++) {
            of[nf][0] *= al0; of[nf][1] *= al0;
            of[nf][2] *= al1; of[nf][3] *= al1;
        }

        // Store P fragments (warp-private rows) to qp_s
        #pragma unroll
        for (int nf = 0; nf < 8; nf++) {
            *(float2*)&qp_s[mr0 * LDQ + nf * 8 + 2 * t] = make_float2(sf[nf][0], sf[nf][1]);
            *(float2*)&qp_s[mr1 * LDQ + nf * 8 + 2 * t] = make_float2(sf[nf][2], sf[nf][3]);
        }
        __syncwarp();

        // PV: O[16x64] += P[16x64] @ V[64x64]
        #pragma unroll
        for (int ks = 0; ks < 8; ks++) {
            uint32_t af[4];
            af[0] = __float_as_uint(qp_s[mr0 * LDQ + t + ks * 8]);
            af[1] = __float_as_uint(qp_s[mr1 * LDQ + t + ks * 8]);
            af[2] = __float_as_uint(qp_s[mr0 * LDQ + t + 4 + ks * 8]);
            af[3] = __float_as_uint(qp_s[mr1 * LDQ + t + 4 + ks * 8]);
            #pragma unroll
            for (int nf = 0; nf < 8; nf++) {
                uint32_t bf[2];
                bf[0] = __float_as_uint(v_s[(t + ks * 8) * LDV + g + nf * 8]);
                bf[1] = __float_as_uint(v_s[(t + 4 + ks * 8) * LDV + g + nf * 8]);
                mma_tf32(of[nf], af, bf);
            }
        }
    }

    // Epilogue: normalize, write [B,S,D] with heads re-interleaved
    const float inv0 = 1.0f / l0r;
    const float inv1 = 1.0f / l1r;
    const size_t r0base = (size_t)(b * SEQ + q0 + mr0) * D_MODEL + h * DEPTH;
    const size_t r1base = (size_t)(b * SEQ + q0 + mr1) * D_MODEL + h * DEPTH;
    #pragma unroll
    for (int nf = 0; nf < 8; nf++) {
        const int col = nf * 8 + 2 * t;
        *(float2*)&g_ao[r0base + col] = make_float2(of[nf][0] * inv0, of[nf][1] * inv0);
        *(float2*)&g_ao[r1base + col] = make_float2(of[nf][2] * inv1, of[nf][3] * inv1);
    }
}

// ---------------------------------------------------------------------------
// Launch
// ---------------------------------------------------------------------------
extern "C" void kernel_launch(void* const* d_in, const int* in_sizes, int n_in,
                              void* d_out, int out_size)
{
    const float* Q  = (const float*)d_in[0];
    const float* K  = (const float*)d_in[1];
    const float* V  = (const float*)d_in[2];
    const float* Wq = (const float*)d_in[3];
    const float* bq = (const float*)d_in[4];
    const float* Wk = (const float*)d_in[5];
    const float* bk = (const float*)d_in[6];
    const float* Wv = (const float*)d_in[7];
    const float* bv = (const float*)d_in[8];
    const float* Wo = (const float*)d_in[9];
    const float* bo = (const float*)d_in[10];
    float* out = (float*)d_out;

    float *gq, *gk, *gv, *gao;
    cudaGetSymbolAddress((void**)&gq,  g_q);
    cudaGetSymbolAddress((void**)&gk,  g_k);
    cudaGetSymbolAddress((void**)&gv,  g_v);
    cudaGetSymbolAddress((void**)&gao, g_ao);

    static bool attr_set = false;
    if (!attr_set) {
        cudaFuncSetAttribute(flash_mma_kernel,
                             cudaFuncAttributeMaxDynamicSharedMemorySize, FL_SMEM);
        attr_set = true;
    }

    const dim3 ggrid(D_MODEL / 128, M_TOT / 128);   // (8, 32)

    // Q/K/V projections (mma.sync tf32) -> head-split scratch
    gemm_mma_kernel<1><<<ggrid, 256>>>(Q, Wq, bq, gq);
    gemm_mma_kernel<1><<<ggrid, 256>>>(K, Wk, bk, gk);
    gemm_mma_kernel<1><<<ggrid, 256>>>(V, Wv, bv, gv);

    // Flash attention (mma.sync tf32)
    flash_mma_kernel<<<dim3(SEQ / 128, BATCH * N_HEADS), 256, FL_SMEM>>>();

    // Output projection (mma.sync tf32) -> d_out
    gemm_mma_kernel<0><<<ggrid, 256>>>(gao, Wo, bo, out);
}